// round 1
// baseline (speedup 1.0000x reference)
#include <cuda_runtime.h>

#define NT 256
#define B_TOTAL 262144

typedef unsigned long long u64;

__device__ __forceinline__ u64 pk2(float a, float b) {
    u64 r;
    asm("mov.b64 %0, {%1, %2};" : "=l"(r) : "r"(__float_as_uint(a)), "r"(__float_as_uint(b)));
    return r;
}
__device__ __forceinline__ void up2(u64 v, float& a, float& b) {
    unsigned lo, hi;
    asm("mov.b64 {%0, %1}, %2;" : "=r"(lo), "=r"(hi) : "l"(v));
    a = __uint_as_float(lo); b = __uint_as_float(hi);
}
__device__ __forceinline__ void fma2(u64& d, u64 a, u64 b) {
    asm("fma.rn.f32x2 %0, %1, %2, %0;" : "+l"(d) : "l"(a), "l"(b));
}
__device__ __forceinline__ void add2(u64& d, u64 a) {
    asm("add.rn.f32x2 %0, %1, %0;" : "+l"(d) : "l"(a));
}
__device__ __forceinline__ float sg(float x) { return __fdividef(1.f, 1.f + __expf(-x)); }
__device__ __forceinline__ float th(float x) {
    float ax = fabsf(x);
    float e = __expf(-2.f * ax);
    float r = __fdividef(1.f - e, 1.f + e);
    return copysignf(r, x);
}

// Shared layout (floats):
//  s_w1  [11][8]  float4 (i,f,g,o)   352
//  s_b1  [8]      float4              32
//  s_w2  [24][16] float4 (i,f,g,o)  1536
//  s_b2  [16]     float4              64
//  s_fc1 [386][128] transposed     49408
//  s_fc1b[128]                       128
//  s_fc2 [128][24] transposed       3072
//  s_fc2b[24]                         24
#define SMEM_FLOATS 54624

__global__ void __launch_bounds__(NT, 1)
lstm_actor_kernel(const float* __restrict__ obs,
                  const float* __restrict__ w_ih1, const float* __restrict__ w_hh1,
                  const float* __restrict__ b_ih1, const float* __restrict__ b_hh1,
                  const float* __restrict__ w_ih2, const float* __restrict__ w_hh2,
                  const float* __restrict__ b_ih2, const float* __restrict__ b_hh2,
                  const float* __restrict__ fc1_w, const float* __restrict__ fc1_b,
                  const float* __restrict__ fc2_w, const float* __restrict__ fc2_b,
                  float* __restrict__ out)
{
    extern __shared__ float smem[];
    float* s_w1   = smem;
    float* s_b1   = s_w1 + 352;
    float* s_w2   = s_b1 + 32;
    float* s_b2   = s_w2 + 1536;
    float* s_fc1  = s_b2 + 64;
    float* s_fc1b = s_fc1 + 49408;
    float* s_fc2  = s_fc1b + 128;
    float* s_fc2b = s_fc2 + 3072;

    const int tid = threadIdx.x;

    // ---- stage weights into shared (layout transforms) ----
    for (int idx = tid; idx < 88; idx += NT) {
        int k = idx >> 3, h = idx & 7;
        float4 v;
        if (k < 3) {
            v.x = w_ih1[h*3+k];      v.y = w_ih1[(8+h)*3+k];
            v.z = w_ih1[(16+h)*3+k]; v.w = w_ih1[(24+h)*3+k];
        } else {
            int kk = k - 3;
            v.x = w_hh1[h*8+kk];      v.y = w_hh1[(8+h)*8+kk];
            v.z = w_hh1[(16+h)*8+kk]; v.w = w_hh1[(24+h)*8+kk];
        }
        ((float4*)s_w1)[idx] = v;
    }
    if (tid < 8) {
        float4 v;
        v.x = b_ih1[tid]    + b_hh1[tid];
        v.y = b_ih1[8+tid]  + b_hh1[8+tid];
        v.z = b_ih1[16+tid] + b_hh1[16+tid];
        v.w = b_ih1[24+tid] + b_hh1[24+tid];
        ((float4*)s_b1)[tid] = v;
    }
    for (int idx = tid; idx < 384; idx += NT) {
        int k = idx >> 4, h = idx & 15;
        float4 v;
        if (k < 8) {
            v.x = w_ih2[h*8+k];      v.y = w_ih2[(16+h)*8+k];
            v.z = w_ih2[(32+h)*8+k]; v.w = w_ih2[(48+h)*8+k];
        } else {
            int kk = k - 8;
            v.x = w_hh2[h*16+kk];      v.y = w_hh2[(16+h)*16+kk];
            v.z = w_hh2[(32+h)*16+kk]; v.w = w_hh2[(48+h)*16+kk];
        }
        ((float4*)s_w2)[idx] = v;
    }
    if (tid < 16) {
        float4 v;
        v.x = b_ih2[tid]    + b_hh2[tid];
        v.y = b_ih2[16+tid] + b_hh2[16+tid];
        v.z = b_ih2[32+tid] + b_hh2[32+tid];
        v.w = b_ih2[48+tid] + b_hh2[48+tid];
        ((float4*)s_b2)[tid] = v;
    }
    for (int idx = tid; idx < 49408; idx += NT) {
        int j = idx / 386;
        int col = idx - j * 386;
        s_fc1[col * 128 + j] = fc1_w[idx];        // coalesced read, scattered smem write
    }
    for (int idx = tid; idx < 128; idx += NT) s_fc1b[idx] = fc1_b[idx];
    for (int idx = tid; idx < 3072; idx += NT) {
        int a = idx >> 7, j = idx & 127;
        s_fc2[j * 24 + a] = fc2_w[idx];
    }
    if (tid < 24) s_fc2b[tid] = fc2_b[tid];
    __syncthreads();

    const ulonglong2* w1v  = (const ulonglong2*)s_w1;
    const ulonglong2* b1v  = (const ulonglong2*)s_b1;
    const ulonglong2* w2v  = (const ulonglong2*)s_w2;
    const ulonglong2* b2v  = (const ulonglong2*)s_b2;
    const ulonglong2* fc1v = (const ulonglong2*)s_fc1;

    const int i = blockIdx.x * NT + tid;
    const float* orow = obs + (size_t)i * 74;

    float h1[8], c1[8], h2[16], c2[16];
    #pragma unroll
    for (int h = 0; h < 8; h++)  { h1[h] = 0.f; c1[h] = 0.f; }
    #pragma unroll
    for (int h = 0; h < 16; h++) { h2[h] = 0.f; c2[h] = 0.f; }
    u64 acc[64];
    #pragma unroll
    for (int j = 0; j < 64; j++) acc[j] = 0ull;

    #pragma unroll 1
    for (int t = 0; t < 24; t++) {
        float xv[3];
        xv[0] = __ldg(orow + t);
        xv[1] = __ldg(orow + 24 + t);
        xv[2] = __ldg(orow + 48 + t);

        // ---- LSTM layer 1 (8 units, 11 inputs) ----
        u64 aif[8], ago[8];
        #pragma unroll
        for (int h = 0; h < 8; h++) { ulonglong2 b = b1v[h]; aif[h] = b.x; ago[h] = b.y; }
        #pragma unroll
        for (int k = 0; k < 11; k++) {
            float m = (k < 3) ? xv[k] : h1[k-3];
            u64 mk = pk2(m, m);
            #pragma unroll
            for (int h = 0; h < 8; h++) {
                ulonglong2 w = w1v[k*8 + h];
                fma2(aif[h], w.x, mk);
                fma2(ago[h], w.y, mk);
            }
        }
        float h1n[8];
        #pragma unroll
        for (int h = 0; h < 8; h++) {
            float gi, gf, gg, go;
            up2(aif[h], gi, gf); up2(ago[h], gg, go);
            float c = sg(gf) * c1[h] + sg(gi) * th(gg);
            c1[h] = c;
            h1n[h] = sg(go) * th(c);
        }

        // ---- LSTM layer 2 (16 units, 24 inputs) in two half-passes (reg pressure) ----
        float h2n[16];
        #pragma unroll
        for (int p = 0; p < 2; p++) {
            const int h0 = p * 8;
            u64 aif2[8], ago2[8];
            #pragma unroll
            for (int jh = 0; jh < 8; jh++) { ulonglong2 b = b2v[h0+jh]; aif2[jh] = b.x; ago2[jh] = b.y; }
            #pragma unroll
            for (int k = 0; k < 24; k++) {
                float m = (k < 8) ? h1n[k] : h2[k-8];
                u64 mk = pk2(m, m);
                #pragma unroll
                for (int jh = 0; jh < 8; jh++) {
                    ulonglong2 w = w2v[k*16 + h0 + jh];
                    fma2(aif2[jh], w.x, mk);
                    fma2(ago2[jh], w.y, mk);
                }
            }
            #pragma unroll
            for (int jh = 0; jh < 8; jh++) {
                float gi, gf, gg, go;
                up2(aif2[jh], gi, gf); up2(ago2[jh], gg, go);
                float c = sg(gf) * c2[h0+jh] + sg(gi) * th(gg);
                c2[h0+jh] = c;
                h2n[h0+jh] = sg(go) * th(c);
            }
        }
        #pragma unroll
        for (int h = 0; h < 8; h++)  h1[h] = h1n[h];
        #pragma unroll
        for (int h = 0; h < 16; h++) h2[h] = h2n[h];

        // ---- FC1 incremental accumulation: acc[j] += h2[h] * fc1_w[j, t*16+h] ----
        #pragma unroll
        for (int h = 0; h < 16; h++) {
            u64 m = pk2(h2n[h], h2n[h]);
            const ulonglong2* wr = fc1v + (size_t)(t*16 + h) * 32;
            #pragma unroll
            for (int jj = 0; jj < 32; jj++) {
                ulonglong2 w = wr[jj];
                fma2(acc[2*jj],   w.x, m);
                fma2(acc[2*jj+1], w.y, m);
            }
        }
    }

    // ---- epilogue: u-features + bias + relu, FC2, softsign ----
    float uu0 = __ldg(orow + 72), uu1 = __ldg(orow + 73);
    u64 u0s = pk2(uu0, uu0), u1s = pk2(uu1, uu1);
    const u64* fc1u = (const u64*)s_fc1;   // 64 u64 per column
    const u64* fbu  = (const u64*)s_fc1b;
    const ulonglong2* fc2v = (const ulonglong2*)s_fc2;

    u64 y[12];
    {
        const ulonglong2* bb = (const ulonglong2*)s_fc2b;
        #pragma unroll
        for (int q = 0; q < 6; q++) { ulonglong2 b = bb[q]; y[2*q] = b.x; y[2*q+1] = b.y; }
    }
    #pragma unroll
    for (int jp = 0; jp < 64; jp++) {
        u64 a = acc[jp];
        fma2(a, fc1u[384*64 + jp], u0s);
        fma2(a, fc1u[385*64 + jp], u1s);
        add2(a, fbu[jp]);
        float v0, v1; up2(a, v0, v1);
        v0 = fmaxf(v0, 0.f); v1 = fmaxf(v1, 0.f);
        u64 vs0 = pk2(v0, v0), vs1 = pk2(v1, v1);
        #pragma unroll
        for (int q = 0; q < 6; q++) {
            ulonglong2 w = fc2v[(2*jp)*6 + q];
            fma2(y[2*q],   w.x, vs0);
            fma2(y[2*q+1], w.y, vs0);
        }
        #pragma unroll
        for (int q = 0; q < 6; q++) {
            ulonglong2 w = fc2v[(2*jp+1)*6 + q];
            fma2(y[2*q],   w.x, vs1);
            fma2(y[2*q+1], w.y, vs1);
        }
    }

    float* op = out + (size_t)i * 24;
    #pragma unroll
    for (int q = 0; q < 6; q++) {
        float a0, a1, a2, a3;
        up2(y[2*q], a0, a1); up2(y[2*q+1], a2, a3);
        float4 o;
        o.x = __fdividef(a0, 1.f + fabsf(a0));
        o.y = __fdividef(a1, 1.f + fabsf(a1));
        o.z = __fdividef(a2, 1.f + fabsf(a2));
        o.w = __fdividef(a3, 1.f + fabsf(a3));
        ((float4*)op)[q] = o;
    }
}

extern "C" void kernel_launch(void* const* d_in, const int* in_sizes, int n_in,
                              void* d_out, int out_size)
{
    const float* obs   = (const float*)d_in[0];
    const float* w_ih1 = (const float*)d_in[1];
    const float* w_hh1 = (const float*)d_in[2];
    const float* b_ih1 = (const float*)d_in[3];
    const float* b_hh1 = (const float*)d_in[4];
    const float* w_ih2 = (const float*)d_in[5];
    const float* w_hh2 = (const float*)d_in[6];
    const float* b_ih2 = (const float*)d_in[7];
    const float* b_hh2 = (const float*)d_in[8];
    const float* fc1_w = (const float*)d_in[9];
    const float* fc1_b = (const float*)d_in[10];
    const float* fc2_w = (const float*)d_in[11];
    const float* fc2_b = (const float*)d_in[12];
    float* out = (float*)d_out;

    const size_t smem_bytes = SMEM_FLOATS * sizeof(float);   // 218496 B < 227 KB limit
    cudaFuncSetAttribute(lstm_actor_kernel,
                         cudaFuncAttributeMaxDynamicSharedMemorySize, (int)smem_bytes);
    lstm_actor_kernel<<<B_TOTAL / NT, NT, smem_bytes>>>(
        obs, w_ih1, w_hh1, b_ih1, b_hh1,
        w_ih2, w_hh2, b_ih2, b_hh2,
        fc1_w, fc1_b, fc2_w, fc2_b, out);
}

// round 7
// speedup vs baseline: 1.5092x; 1.5092x over previous
#include <cuda_runtime.h>
#include <cstdint>

#define NT 256
#define B_TOTAL 262144
#define KPAD 448          // 386 padded to 14 * 32
#define NCHUNK 14

typedef unsigned long long u64;

// ---------------- scratch (static device globals: allowed) ----------------
__device__ float g_feats[(size_t)B_TOTAL * KPAD];   // [elem][448], tf32-rounded
__device__ float g_fc1p[128 * KPAD];                // [out][448], tf32-rounded, zero-padded

// ---------------- small helpers ----------------
__device__ __forceinline__ u64 pk2(float a, float b) {
    u64 r;
    asm("mov.b64 %0, {%1, %2};" : "=l"(r) : "r"(__float_as_uint(a)), "r"(__float_as_uint(b)));
    return r;
}
__device__ __forceinline__ void up2(u64 v, float& a, float& b) {
    unsigned lo, hi;
    asm("mov.b64 {%0, %1}, %2;" : "=r"(lo), "=r"(hi) : "l"(v));
    a = __uint_as_float(lo); b = __uint_as_float(hi);
}
__device__ __forceinline__ void fma2(u64& d, u64 a, u64 b) {
    asm("fma.rn.f32x2 %0, %1, %2, %0;" : "+l"(d) : "l"(a), "l"(b));
}
__device__ __forceinline__ float sg(float x) { return __fdividef(1.f, 1.f + __expf(-x)); }
__device__ __forceinline__ float th(float x) {
    float ax = fabsf(x);
    float e = __expf(-2.f * ax);
    float r = __fdividef(1.f - e, 1.f + e);
    return copysignf(r, x);
}
__device__ __forceinline__ float tfr(float x) {   // round-to-nearest tf32
    unsigned u; asm("cvt.rna.tf32.f32 %0, %1;" : "=r"(u) : "f"(x));
    return __uint_as_float(u);
}
__device__ __forceinline__ void cpasync16(uint32_t dst, const void* src) {
    asm volatile("cp.async.cg.shared.global [%0], [%1], 16;" :: "r"(dst), "l"(src) : "memory");
}
__device__ __forceinline__ uint32_t smem_u32(const void* p) {
    uint32_t a;
    asm("{ .reg .u64 t; cvta.to.shared.u64 t, %1; cvt.u32.u64 %0, t; }" : "=r"(a) : "l"(p));
    return a;
}
__device__ __forceinline__ void mma_tf32(float4& c, uint32_t a0, uint32_t a1,
                                         uint32_t a2, uint32_t a3,
                                         uint32_t b0, uint32_t b1) {
    asm volatile(
        "mma.sync.aligned.m16n8k8.row.col.f32.tf32.tf32.f32 "
        "{%0,%1,%2,%3}, {%4,%5,%6,%7}, {%8,%9}, {%0,%1,%2,%3};"
        : "+f"(c.x), "+f"(c.y), "+f"(c.z), "+f"(c.w)
        : "r"(a0), "r"(a1), "r"(a2), "r"(a3), "r"(b0), "r"(b1));
}

// ==========================================================================
// Kernel A: 2-layer LSTM, 2 elements per thread, writes feats rows
// ==========================================================================
__global__ void __launch_bounds__(NT, 1)
lstm_kernel(const float* __restrict__ obs,
            const float* __restrict__ w_ih1, const float* __restrict__ w_hh1,
            const float* __restrict__ b_ih1, const float* __restrict__ b_hh1,
            const float* __restrict__ w_ih2, const float* __restrict__ w_hh2,
            const float* __restrict__ b_ih2, const float* __restrict__ b_hh2)
{
    __shared__ __align__(16) float smem[1984];
    float* s_w1 = smem;          // [11][8] float4 (i,f,g,o)  352
    float* s_b1 = smem + 352;    // [8] float4                 32
    float* s_w2 = smem + 384;    // [24][16] float4          1536
    float* s_b2 = smem + 1920;   // [16] float4                64

    const int tid = threadIdx.x;

    for (int idx = tid; idx < 88; idx += NT) {
        int k = idx >> 3, h = idx & 7;
        float4 v;
        if (k < 3) {
            v.x = w_ih1[h*3+k];      v.y = w_ih1[(8+h)*3+k];
            v.z = w_ih1[(16+h)*3+k]; v.w = w_ih1[(24+h)*3+k];
        } else {
            int kk = k - 3;
            v.x = w_hh1[h*8+kk];      v.y = w_hh1[(8+h)*8+kk];
            v.z = w_hh1[(16+h)*8+kk]; v.w = w_hh1[(24+h)*8+kk];
        }
        ((float4*)s_w1)[idx] = v;
    }
    if (tid < 8) {
        float4 v;
        v.x = b_ih1[tid]    + b_hh1[tid];
        v.y = b_ih1[8+tid]  + b_hh1[8+tid];
        v.z = b_ih1[16+tid] + b_hh1[16+tid];
        v.w = b_ih1[24+tid] + b_hh1[24+tid];
        ((float4*)s_b1)[tid] = v;
    }
    for (int idx = tid; idx < 384; idx += NT) {
        int k = idx >> 4, h = idx & 15;
        float4 v;
        if (k < 8) {
            v.x = w_ih2[h*8+k];      v.y = w_ih2[(16+h)*8+k];
            v.z = w_ih2[(32+h)*8+k]; v.w = w_ih2[(48+h)*8+k];
        } else {
            int kk = k - 8;
            v.x = w_hh2[h*16+kk];      v.y = w_hh2[(16+h)*16+kk];
            v.z = w_hh2[(32+h)*16+kk]; v.w = w_hh2[(48+h)*16+kk];
        }
        ((float4*)s_w2)[idx] = v;
    }
    if (tid < 16) {
        float4 v;
        v.x = b_ih2[tid]    + b_hh2[tid];
        v.y = b_ih2[16+tid] + b_hh2[16+tid];
        v.z = b_ih2[32+tid] + b_hh2[32+tid];
        v.w = b_ih2[48+tid] + b_hh2[48+tid];
        ((float4*)s_b2)[tid] = v;
    }
    __syncthreads();

    const ulonglong2* w1v = (const ulonglong2*)s_w1;
    const ulonglong2* b1v = (const ulonglong2*)s_b1;
    const ulonglong2* w2v = (const ulonglong2*)s_w2;
    const ulonglong2* b2v = (const ulonglong2*)s_b2;

    const int e0 = blockIdx.x * (2 * NT) + tid;
    const int e1 = e0 + NT;
    const float* o0 = obs + (size_t)e0 * 74;
    const float* o1 = obs + (size_t)e1 * 74;
    float* f0 = g_feats + (size_t)e0 * KPAD;
    float* f1 = g_feats + (size_t)e1 * KPAD;

    float h1[2][8], c1[2][8], h2[2][16], c2[2][16];
    #pragma unroll
    for (int h = 0; h < 8; h++)  { h1[0][h]=h1[1][h]=0.f; c1[0][h]=c1[1][h]=0.f; }
    #pragma unroll
    for (int h = 0; h < 16; h++) { h2[0][h]=h2[1][h]=0.f; c2[0][h]=c2[1][h]=0.f; }

    #pragma unroll 1
    for (int t = 0; t < 24; t++) {
        float x0[3], x1[3];
        x0[0] = __ldg(o0 + t); x0[1] = __ldg(o0 + 24 + t); x0[2] = __ldg(o0 + 48 + t);
        x1[0] = __ldg(o1 + t); x1[1] = __ldg(o1 + 24 + t); x1[2] = __ldg(o1 + 48 + t);

        // ---- LSTM layer 1 ----
        u64 aif[2][8], ago[2][8];
        #pragma unroll
        for (int h = 0; h < 8; h++) {
            ulonglong2 b = b1v[h];
            aif[0][h] = b.x; ago[0][h] = b.y;
            aif[1][h] = b.x; ago[1][h] = b.y;
        }
        #pragma unroll
        for (int k = 0; k < 11; k++) {
            float m0 = (k < 3) ? x0[k] : h1[0][k-3];
            float m1 = (k < 3) ? x1[k] : h1[1][k-3];
            u64 mk0 = pk2(m0, m0), mk1 = pk2(m1, m1);
            #pragma unroll
            for (int h = 0; h < 8; h++) {
                ulonglong2 w = w1v[k*8 + h];
                fma2(aif[0][h], w.x, mk0); fma2(ago[0][h], w.y, mk0);
                fma2(aif[1][h], w.x, mk1); fma2(ago[1][h], w.y, mk1);
            }
        }
        float h1n[2][8];
        #pragma unroll
        for (int e = 0; e < 2; e++)
            #pragma unroll
            for (int h = 0; h < 8; h++) {
                float gi, gf, gg, go;
                up2(aif[e][h], gi, gf); up2(ago[e][h], gg, go);
                float c = sg(gf) * c1[e][h] + sg(gi) * th(gg);
                c1[e][h] = c;
                h1n[e][h] = sg(go) * th(c);
            }

        // ---- LSTM layer 2, two half-passes of 8 units ----
        float h2n[2][16];
        #pragma unroll
        for (int p = 0; p < 2; p++) {
            const int h0 = p * 8;
            u64 a2[2][8], g2[2][8];
            #pragma unroll
            for (int jh = 0; jh < 8; jh++) {
                ulonglong2 b = b2v[h0 + jh];
                a2[0][jh] = b.x; g2[0][jh] = b.y;
                a2[1][jh] = b.x; g2[1][jh] = b.y;
            }
            #pragma unroll
            for (int k = 0; k < 24; k++) {
                float m0 = (k < 8) ? h1n[0][k] : h2[0][k-8];
                float m1 = (k < 8) ? h1n[1][k] : h2[1][k-8];
                u64 mk0 = pk2(m0, m0), mk1 = pk2(m1, m1);
                #pragma unroll
                for (int jh = 0; jh < 8; jh++) {
                    ulonglong2 w = w2v[k*16 + h0 + jh];
                    fma2(a2[0][jh], w.x, mk0); fma2(g2[0][jh], w.y, mk0);
                    fma2(a2[1][jh], w.x, mk1); fma2(g2[1][jh], w.y, mk1);
                }
            }
            #pragma unroll
            for (int e = 0; e < 2; e++)
                #pragma unroll
                for (int jh = 0; jh < 8; jh++) {
                    float gi, gf, gg, go;
                    up2(a2[e][jh], gi, gf); up2(g2[e][jh], gg, go);
                    float c = sg(gf) * c2[e][h0+jh] + sg(gi) * th(gg);
                    c2[e][h0+jh] = c;
                    h2n[e][h0+jh] = sg(go) * th(c);
                }
        }
        #pragma unroll
        for (int h = 0; h < 8; h++)  { h1[0][h] = h1n[0][h]; h1[1][h] = h1n[1][h]; }
        #pragma unroll
        for (int h = 0; h < 16; h++) { h2[0][h] = h2n[0][h]; h2[1][h] = h2n[1][h]; }

        // ---- store h2 (tf32-rounded) into feats ----
        #pragma unroll
        for (int e = 0; e < 2; e++) {
            float* fr = (e == 0 ? f0 : f1) + t * 16;
            #pragma unroll
            for (int q = 0; q < 4; q++) {
                float4 v;
                v.x = tfr(h2n[e][4*q+0]); v.y = tfr(h2n[e][4*q+1]);
                v.z = tfr(h2n[e][4*q+2]); v.w = tfr(h2n[e][4*q+3]);
                ((float4*)fr)[q] = v;
            }
        }
    }

    // ---- tail: u features + zero padding (cols 384..447) ----
    #pragma unroll
    for (int e = 0; e < 2; e++) {
        const float* oe = (e == 0) ? o0 : o1;
        float* fe = (e == 0) ? f0 : f1;
        float4 v; v.x = tfr(__ldg(oe + 72)); v.y = tfr(__ldg(oe + 73)); v.z = 0.f; v.w = 0.f;
        ((float4*)(fe + 384))[0] = v;
        float4 z; z.x = z.y = z.z = z.w = 0.f;
        #pragma unroll
        for (int q = 0; q < 15; q++) ((float4*)(fe + 388))[q] = z;
    }
}

// ==========================================================================
// Kernel P: pad + tf32-round fc1 weights
// ==========================================================================
__global__ void pad_kernel(const float* __restrict__ fc1_w)
{
    int idx = blockIdx.x * blockDim.x + threadIdx.x;
    if (idx >= 128 * KPAD) return;
    int j = idx / KPAD, k = idx - j * KPAD;
    g_fc1p[idx] = (k < 386) ? tfr(fc1_w[j * 386 + k]) : 0.f;
}

// ==========================================================================
// Kernel B: tf32 mma.sync GEMM (M-tile 256, N=128, K=448) + FC2 epilogue
// ==========================================================================
// dynamic smem (floats):
//   A bufs: 2 x (256 rows x 36)  = 18432   (stride 36 kills frag-load conflicts)
//   B bufs: 2 x (128 rows x 36)  =  9216   (offset 18432)
//   C scratch (reused region):    256 x 133 = 34048 floats total dyn size
#define A_STRIDE 36
#define C_STRIDE 133
#define FCDYN_FLOATS (256 * C_STRIDE)

__global__ void __launch_bounds__(256, 1)
fc_kernel(const float* __restrict__ fc1_b,
          const float* __restrict__ fc2_w, const float* __restrict__ fc2_b,
          float* __restrict__ out)
{
    extern __shared__ float smf[];
    __shared__ __align__(16) float s_fc2[3072];    // [k][a] transposed
    __shared__ __align__(16) float s_fc1b[128];
    __shared__ __align__(16) float s_fc2b[24];

    const int tid  = threadIdx.x;
    const int wid  = tid >> 5;
    const int lane = tid & 31;
    const int laneRow = lane >> 2;     // 0..7
    const int laneCol = lane & 3;      // 0..3
    const int wbase = wid * 32;        // warp's 32-row slice of the 256-row tile

    const uint32_t sbase = smem_u32(smf);
    const uint32_t aBuf[2] = { sbase,               sbase + 9216u * 4u };
    const uint32_t bBuf[2] = { sbase + 18432u * 4u, sbase + (18432u + 4608u) * 4u };

    // stage FC2 weights + biases
    for (int idx = tid; idx < 3072; idx += 256) {
        int a = idx >> 7, k = idx & 127;
        s_fc2[k * 24 + a] = fc2_w[idx];
    }
    if (tid < 128) s_fc1b[tid] = fc1_b[tid];
    if (tid < 24)  s_fc2b[tid] = fc2_b[tid];

    const int m0 = blockIdx.x * 256;
    const float* arow = g_feats + (size_t)(m0 + tid) * KPAD;   // thread copies row tid
    const int bRow  = tid >> 1;
    const int bHalf = (tid & 1) * 16;
    const float* brow = g_fc1p + (size_t)bRow * KPAD + bHalf;

    // ---- prefetch chunk 0 ----
    {
        uint32_t da = aBuf[0] + (uint32_t)tid * A_STRIDE * 4;
        #pragma unroll
        for (int c = 0; c < 8; c++) cpasync16(da + c * 16, arow + c * 4);
        uint32_t db = bBuf[0] + ((uint32_t)bRow * A_STRIDE + bHalf) * 4;
        #pragma unroll
        for (int c = 0; c < 4; c++) cpasync16(db + c * 16, brow + c * 4);
        asm volatile("cp.async.commit_group;" ::: "memory");
    }

    float4 acc[2][16];
    #pragma unroll
    for (int ms = 0; ms < 2; ms++)
        #pragma unroll
        for (int nt = 0; nt < 16; nt++) acc[ms][nt] = make_float4(0.f, 0.f, 0.f, 0.f);

    #pragma unroll 1
    for (int ch = 0; ch < NCHUNK; ch++) {
        if (ch + 1 < NCHUNK) {
            const int nb = (ch + 1) & 1;
            uint32_t da = aBuf[nb] + (uint32_t)tid * A_STRIDE * 4;
            const float* as = arow + (ch + 1) * 32;
            #pragma unroll
            for (int c = 0; c < 8; c++) cpasync16(da + c * 16, as + c * 4);
            uint32_t db = bBuf[nb] + ((uint32_t)bRow * A_STRIDE + bHalf) * 4;
            const float* bs = brow + (ch + 1) * 32;
            #pragma unroll
            for (int c = 0; c < 4; c++) cpasync16(db + c * 16, bs + c * 4);
            asm volatile("cp.async.commit_group;" ::: "memory");
            asm volatile("cp.async.wait_group 1;" ::: "memory");
        } else {
            asm volatile("cp.async.wait_group 0;" ::: "memory");
        }
        __syncthreads();

        const int buf = ch & 1;
        const float* A  = smf + buf * 9216;
        const float* Bp = smf + 18432 + buf * 4608;

        #pragma unroll
        for (int kk = 0; kk < 4; kk++) {
            const int kc = kk * 8 + laneCol;
            uint32_t b0[16], b1[16];
            #pragma unroll
            for (int nt = 0; nt < 16; nt++) {
                const float* bp = Bp + (nt * 8 + laneRow) * A_STRIDE + kc;
                b0[nt] = __float_as_uint(bp[0]);
                b1[nt] = __float_as_uint(bp[4]);
            }
            #pragma unroll
            for (int ms = 0; ms < 2; ms++) {
                const float* ap = A + (wbase + ms * 16 + laneRow) * A_STRIDE + kc;
                uint32_t a0 = __float_as_uint(ap[0]);
                uint32_t a1 = __float_as_uint(ap[8 * A_STRIDE]);
                uint32_t a2 = __float_as_uint(ap[4]);
                uint32_t a3 = __float_as_uint(ap[8 * A_STRIDE + 4]);
                #pragma unroll
                for (int nt = 0; nt < 16; nt++)
                    mma_tf32(acc[ms][nt], a0, a1, a2, a3, b0[nt], b1[nt]);
            }
        }
        __syncthreads();
    }

    // ---- write C into smem (row-major, stride 133; scalar stores = aligned) ----
    #pragma unroll
    for (int ms = 0; ms < 2; ms++) {
        const int rbase = wbase + ms * 16 + laneRow;
        #pragma unroll
        for (int nt = 0; nt < 16; nt++) {
            const int col = nt * 8 + 2 * laneCol;
            smf[(size_t)rbase * C_STRIDE + col]           = acc[ms][nt].x;
            smf[(size_t)rbase * C_STRIDE + col + 1]       = acc[ms][nt].y;
            smf[(size_t)(rbase + 8) * C_STRIDE + col]     = acc[ms][nt].z;
            smf[(size_t)(rbase + 8) * C_STRIDE + col + 1] = acc[ms][nt].w;
        }
    }
    __syncthreads();

    // thread tid handles output row m0 + tid
    const float* crow = smf + (size_t)tid * C_STRIDE;
    u64 y[12];
    {
        const ulonglong2* bb = (const ulonglong2*)s_fc2b;
        #pragma unroll
        for (int q = 0; q < 6; q++) { ulonglong2 b = bb[q]; y[2*q] = b.x; y[2*q+1] = b.y; }
    }
    const ulonglong2* fc2v = (const ulonglong2*)s_fc2;
    #pragma unroll 4
    for (int j = 0; j < 128; j++) {
        float v = crow[j] + s_fc1b[j];
        v = fmaxf(v, 0.f);
        u64 vk = pk2(v, v);
        const ulonglong2* wr = fc2v + j * 6;
        #pragma unroll
        for (int q = 0; q < 6; q++) {
            ulonglong2 w = wr[q];
            fma2(y[2*q],   w.x, vk);
            fma2(y[2*q+1], w.y, vk);
        }
    }
    float* op = out + (size_t)(m0 + tid) * 24;
    #pragma unroll
    for (int q = 0; q < 6; q++) {
        float a0, a1, a2, a3;
        up2(y[2*q], a0, a1); up2(y[2*q+1], a2, a3);
        float4 o;
        o.x = __fdividef(a0, 1.f + fabsf(a0));
        o.y = __fdividef(a1, 1.f + fabsf(a1));
        o.z = __fdividef(a2, 1.f + fabsf(a2));
        o.w = __fdividef(a3, 1.f + fabsf(a3));
        ((float4*)op)[q] = o;
    }
}

// ==========================================================================
extern "C" void kernel_launch(void* const* d_in, const int* in_sizes, int n_in,
                              void* d_out, int out_size)
{
    const float* obs   = (const float*)d_in[0];
    const float* w_ih1 = (const float*)d_in[1];
    const float* w_hh1 = (const float*)d_in[2];
    const float* b_ih1 = (const float*)d_in[3];
    const float* b_hh1 = (const float*)d_in[4];
    const float* w_ih2 = (const float*)d_in[5];
    const float* w_hh2 = (const float*)d_in[6];
    const float* b_ih2 = (const float*)d_in[7];
    const float* b_hh2 = (const float*)d_in[8];
    const float* fc1_w = (const float*)d_in[9];
    const float* fc1_b = (const float*)d_in[10];
    const float* fc2_w = (const float*)d_in[11];
    const float* fc2_b = (const float*)d_in[12];
    float* out = (float*)d_out;

    lstm_kernel<<<B_TOTAL / (2 * NT), NT>>>(obs, w_ih1, w_hh1, b_ih1, b_hh1,
                                            w_ih2, w_hh2, b_ih2, b_hh2);

    pad_kernel<<<(128 * KPAD + 1023) / 1024, 1024>>>(fc1_w);

    const size_t dyn = FCDYN_FLOATS * sizeof(float);   // 136192 B
    cudaFuncSetAttribute(fc_kernel, cudaFuncAttributeMaxDynamicSharedMemorySize, (int)dyn);
    fc_kernel<<<B_TOTAL / 256, 256, dyn>>>(fc1_b, fc2_w, fc2_b, out);
}